// round 17
// baseline (speedup 1.0000x reference)
#include <cuda_runtime.h>
#include <math.h>
#include <cstdint>

#define BATCH  2
#define NSEQ   2048
#define DIM    512
#define HEADS  8
#define DHEAD  32
#define INNER  256
#define ROWS   (BATCH*NSEQ)   // 4096

// ---------------- scratch (device globals) ----------------------------------
__device__ uint32_t g_xn_h[ROWS*DIM/2], g_xn_l[ROWS*DIM/2];   // LN out fp16 h/l
__device__ uint32_t g_w1h[(DIM/2)*(3*INNER)];                 // w_qkv fp16
__device__ uint32_t g_oh[ROWS*INNER/2],  g_ol[ROWS*INNER/2];  // attn O fp16 h/l
__device__ uint32_t g_w2h[(INNER/2)*DIM];                     // w_out fp16
__device__ uint32_t g_qp[BATCH*HEADS*NSEQ*16];   // Q fp16x2 pairs along d, pre-scaled
__device__ uint32_t g_kp[BATCH*HEADS*NSEQ*16];   // K fp16x2 pairs along d
__device__ float    g_v [BATCH*HEADS*NSEQ*DHEAD];// V fp32 [bh][n][d]
__device__ uint32_t g_vp[BATCH*HEADS*32*1024];   // V fp16x2 [bh][d][jp] pairs along n

__device__ __forceinline__ uint32_t fau(float x) { return __float_as_uint(x); }

__device__ __forceinline__ uint32_t packf16(float hi, float lo) {
    uint32_t r; asm("cvt.rn.f16x2.f32 %0, %1, %2;" : "=r"(r) : "f"(hi), "f"(lo)); return r;
}
__device__ __forceinline__ float f16lo(uint32_t p) {
    float f; asm("{.reg .b16 l,h; mov.b32 {l,h}, %1; cvt.f32.f16 %0, l;}" : "=f"(f) : "r"(p)); return f;
}
__device__ __forceinline__ float f16hi(uint32_t p) {
    float f; asm("{.reg .b16 l,h; mov.b32 {l,h}, %1; cvt.f32.f16 %0, h;}" : "=f"(f) : "r"(p)); return f;
}

__device__ __forceinline__ uint32_t smem_u32(const void* p) {
    uint32_t a;
    asm("{ .reg .u64 t; cvta.to.shared.u64 t, %1; cvt.u32.u64 %0, t; }" : "=r"(a) : "l"(p));
    return a;
}
__device__ __forceinline__ void cp16(uint32_t saddr, const void* g) {
    asm volatile("cp.async.cg.shared.global [%0], [%1], 16;" :: "r"(saddr), "l"(g));
}
#define CP_COMMIT() asm volatile("cp.async.commit_group;" ::: "memory")
#define CP_WAIT(n)  asm volatile("cp.async.wait_group %0;" :: "n"(n) : "memory")

// mma m16n8k16 fp16 (GEMMs + attention)
__device__ __forceinline__ void mma_f16(float* d, const uint32_t* a, const uint32_t* b) {
    asm volatile(
        "mma.sync.aligned.m16n8k16.row.col.f32.f16.f16.f32 "
        "{%0,%1,%2,%3}, {%4,%5,%6,%7}, {%8,%9}, {%0,%1,%2,%3};"
        : "+f"(d[0]), "+f"(d[1]), "+f"(d[2]), "+f"(d[3])
        : "r"(a[0]), "r"(a[1]), "r"(a[2]), "r"(a[3]), "r"(b[0]), "r"(b[1]));
}

// ---------------- 0) weight pack: f32 [K][N] -> fp16x2 [K/2][N] -------------
__global__ __launch_bounds__(256) void pack_w_kernel(const float* __restrict__ w,
                                                     uint32_t* __restrict__ wh,
                                                     int N, int total)
{
    int idx = blockIdx.x*256 + threadIdx.x;
    if (idx >= total) return;
    int kp = idx / N;
    int n  = idx - kp*N;
    float v0 = w[(size_t)(2*kp  )*N + n];
    float v1 = w[(size_t)(2*kp+1)*N + n];
    wh[idx] = packf16(v1, v0);
}

// ---------------- 0b) V repack: [bh][n][d] f32 -> [bh][d][jp] fp16x2 --------
__global__ __launch_bounds__(256) void vpack_kernel()
{
    __shared__ float vs[128][33];
    int tid = threadIdx.x;
    int bh  = blockIdx.y;
    int n0  = blockIdx.x * 128;

    #pragma unroll
    for (int u = 0; u < 4; ++u) {
        int f   = u*256 + tid;
        int row = f >> 3;
        int dg  = (f & 7) * 4;
        float4 vv = *(const float4*)(g_v + ((size_t)bh*NSEQ + n0 + row)*DHEAD + dg);
        vs[row][dg+0] = vv.x; vs[row][dg+1] = vv.y;
        vs[row][dg+2] = vv.z; vs[row][dg+3] = vv.w;
    }
    __syncthreads();

    int d  = tid >> 3;
    int j8 = (tid & 7) * 8;
    uint32_t* dst = g_vp + ((size_t)bh*32 + d)*1024 + (n0 >> 1) + j8;
    #pragma unroll
    for (int k = 0; k < 8; ++k) {
        int jp = j8 + k;
        dst[k] = packf16(vs[2*jp+1][d], vs[2*jp][d]);
    }
}

// ---------------- 1) LayerNorm (writes fp16x2 h/l) --------------------------
__global__ __launch_bounds__(128) void ln_kernel(const float* __restrict__ x,
                                                 const float* __restrict__ gamma)
{
    int row = blockIdx.x;
    int t   = threadIdx.x;
    const float* xr = x + (size_t)row*DIM;

    float4 xv = *(const float4*)(xr + t*4);
    float s  = xv.x + xv.y + xv.z + xv.w;
    float ss = xv.x*xv.x + xv.y*xv.y + xv.z*xv.z + xv.w*xv.w;

    #pragma unroll
    for (int ofs = 16; ofs >= 1; ofs >>= 1) {
        s  += __shfl_xor_sync(0xffffffffu, s,  ofs);
        ss += __shfl_xor_sync(0xffffffffu, ss, ofs);
    }
    __shared__ float rs[4], rss[4];
    int lane = t & 31, wid = t >> 5;
    if (lane == 0) { rs[wid] = s; rss[wid] = ss; }
    __syncthreads();
    s  = rs[0]  + rs[1]  + rs[2]  + rs[3];
    ss = rss[0] + rss[1] + rss[2] + rss[3];

    float mu   = s * (1.0f/DIM);
    float var  = ss * (1.0f/DIM) - mu*mu;
    float rstd = rsqrtf(var + 1e-5f);

    float4 g = *(const float4*)(gamma + t*4);
    float4 o;
    o.x = (xv.x - mu) * rstd * g.x;
    o.y = (xv.y - mu) * rstd * g.y;
    o.z = (xv.z - mu) * rstd * g.z;
    o.w = (xv.w - mu) * rstd * g.w;

    uint32_t h0 = packf16(o.y, o.x);
    uint32_t h1 = packf16(o.w, o.z);
    uint32_t l0 = packf16(o.y - f16hi(h0), o.x - f16lo(h0));
    uint32_t l1 = packf16(o.w - f16hi(h1), o.z - f16lo(h1));
    *(uint2*)&g_xn_h[(size_t)row*256 + 2*t] = make_uint2(h0, h1);
    *(uint2*)&g_xn_l[(size_t)row*256 + 2*t] = make_uint2(l0, l1);
}

// ====== fp16 2-term split GEMM core (R15 proven) ============================
template<int KP, int NSTRIDE>
__device__ __forceinline__ void gemm_f16_core(
    const uint32_t* __restrict__ Ah, const uint32_t* __restrict__ Al,
    const uint32_t* __restrict__ Bh,
    uint32_t (*sm)[5120], float c[2][4][4])
{
    const int tid  = threadIdx.x;
    const int lane = tid & 31;
    const int w    = tid >> 5;
    const int wm   = w >> 1, wn = w & 1;
    const int g    = lane >> 2, q = lane & 3;
    const int bm   = blockIdx.y * 128;
    const int bn   = blockIdx.x * 64;
    const int KT   = KP / 16;

    const int arow = tid >> 2, ac4 = tid & 3;
    const int brow = tid >> 4, bc4 = tid & 15;
    const uint32_t aswz = (uint32_t)(ac4 ^ ((arow >> 1) & 3));
    const uint32_t bswz = (uint32_t)(bc4 ^ ((brow & 3) << 1));

    uint32_t sbase[2] = { smem_u32(&sm[0][0]), smem_u32(&sm[1][0]) };

    #define GPREF(SB, T)                                                        \
    do {                                                                        \
        cp16((SB) + (uint32_t)arow*64u + aswz*16u,                              \
             Ah + (size_t)(bm+arow)*KP + (T)*16 + ac4*4);                       \
        cp16((SB) + (uint32_t)(arow+64)*64u + aswz*16u,                         \
             Ah + (size_t)(bm+arow+64)*KP + (T)*16 + ac4*4);                    \
        cp16((SB) + 8192u + (uint32_t)arow*64u + aswz*16u,                      \
             Al + (size_t)(bm+arow)*KP + (T)*16 + ac4*4);                       \
        cp16((SB) + 8192u + (uint32_t)(arow+64)*64u + aswz*16u,                 \
             Al + (size_t)(bm+arow+64)*KP + (T)*16 + ac4*4);                    \
        cp16((SB) + 16384u + (uint32_t)brow*256u + bswz*16u,                    \
             Bh + (size_t)((T)*16+brow)*NSTRIDE + bn + bc4*4);                  \
        CP_COMMIT();                                                            \
    } while (0)

    GPREF(sbase[0], 0);

    for (int t = 0; t < KT; ++t) {
        if (t + 1 < KT) { GPREF(sbase[(t+1) & 1], t+1); CP_WAIT(1); }
        else            { CP_WAIT(0); }
        __syncthreads();

        const uint32_t* sAh = &sm[t & 1][0];
        const uint32_t* sAl = sAh + 2048;
        const uint32_t* sBh = sAh + 4096;

        #pragma unroll
        for (int ks = 0; ks < 2; ++ks) {
            uint32_t ah[2][4], al[2][4];
            #pragma unroll
            for (int i = 0; i < 2; ++i) {
                #pragma unroll
                for (int r = 0; r < 4; ++r) {
                    int row = wm*32 + i*16 + g + 8*(r & 1);
                    int c4  = (ks*2 + (r >> 1)) ^ ((row >> 1) & 3);
                    int idx = row*16 + c4*4 + q;
                    ah[i][r] = sAh[idx];
                    al[i][r] = sAl[idx];
                }
            }
            uint32_t bh[4][2];
            #pragma unroll
            for (int j = 0; j < 4; ++j) {
                #pragma unroll
                for (int r = 0; r < 2; ++r) {
                    int kp = ks*8 + q + 4*r;
                    int n  = wn*32 + j*8 + g;
                    int c4 = (n >> 2) ^ ((kp & 3) << 1);
                    bh[j][r] = sBh[kp*64 + c4*4 + (n & 3)];
                }
            }
            #pragma unroll
            for (int i = 0; i < 2; ++i)
                #pragma unroll
                for (int j = 0; j < 4; ++j) {
                    mma_f16(c[i][j], ah[i], bh[j]);
                    mma_f16(c[i][j], al[i], bh[j]);
                }
        }
        __syncthreads();
    }
    #undef GPREF
}

// ---------------- 2) QKV GEMM (fp16 2-term) ---------------------------------
__global__ __launch_bounds__(256) void gemm_qkv_tc()
{
    __shared__ uint32_t sm[2][5120];
    float c[2][4][4] = {};
    gemm_f16_core<DIM/2, 3*INNER>(g_xn_h, g_xn_l, g_w1h, sm, c);

    int tid  = threadIdx.x;
    int lane = tid & 31;
    int w    = tid >> 5;
    int wm   = w >> 1, wn = w & 1;
    int g    = lane >> 2, q = lane & 3;
    int bm   = blockIdx.y * 128;
    int bn   = blockIdx.x * 64;

    #pragma unroll
    for (int i = 0; i < 2; ++i) {
        int row0 = bm + wm*32 + i*16 + g;
        #pragma unroll
        for (int j = 0; j < 4; ++j) {
            int col  = bn + wn*32 + j*8 + 2*q;
            int part = col >> 8;
            int rest = col & 255;
            int h    = rest >> 5;
            int d    = rest & 31;
            #pragma unroll
            for (int r = 0; r < 2; ++r) {
                int rm = row0 + r*8;
                int b_ = rm >> 11;
                int n  = rm & 2047;
                int bh = b_*HEADS + h;
                float v0 = c[i][j][r*2+0];
                float v1 = c[i][j][r*2+1];
                if (part == 0) {
                    const float scl = 0.17677669529663687f;
                    g_qp[((size_t)bh*NSEQ + n)*16 + (d >> 1)] =
                        packf16(v1*scl, v0*scl);
                } else if (part == 1) {
                    g_kp[((size_t)bh*NSEQ + n)*16 + (d >> 1)] = packf16(v1, v0);
                } else {
                    float2 o; o.x = v0; o.y = v1;
                    *(float2*)(g_v + ((size_t)bh*NSEQ + n)*DHEAD + d) = o;
                }
            }
        }
    }
}

// ---------------- 4) Out projection (fp16 2-term) ---------------------------
__global__ __launch_bounds__(256) void gemm_out_tc(const float* __restrict__ bvec,
                                                   float* __restrict__ out)
{
    __shared__ uint32_t sm[2][5120];
    float c[2][4][4] = {};
    gemm_f16_core<INNER/2, DIM>(g_oh, g_ol, g_w2h, sm, c);

    int tid  = threadIdx.x;
    int lane = tid & 31;
    int w    = tid >> 5;
    int wm   = w >> 1, wn = w & 1;
    int g    = lane >> 2, q = lane & 3;
    int bm   = blockIdx.y * 128;
    int bn   = blockIdx.x * 64;

    #pragma unroll
    for (int i = 0; i < 2; ++i) {
        int row0 = bm + wm*32 + i*16 + g;
        #pragma unroll
        for (int j = 0; j < 4; ++j) {
            int col = bn + wn*32 + j*8 + 2*q;
            float2 bb = *(const float2*)(bvec + col);
            #pragma unroll
            for (int r = 0; r < 2; ++r) {
                int rm = row0 + r*8;
                float2 o;
                o.x = c[i][j][r*2+0] + bb.x;
                o.y = c[i][j][r*2+1] + bb.y;
                *(float2*)(out + (size_t)rm*DIM + col) = o;
            }
        }
    }
}

// ---------------- 3) Attention: batch-fused, fp16 k16, cp.async pipelined ---
// grid (16 i-tiles, 8 heads); each CTA does BOTH batches, reading the shared
// bias tile once. Stage layout (u32): K0@0(1280) K1@1280 V0@2560(1152)
// V1@3712; kv stage=4864; bias f32 [128][16 f4 swz] @9728 + stg*8192.
#define ATT_SMEM_BYTES (26112*4)

__global__ __launch_bounds__(256) void attn_mma_kernel(const float* __restrict__ bias)
{
    extern __shared__ float smem[];
    uint32_t* smemu = (uint32_t*)smem;

    int tid  = threadIdx.x;
    int w    = tid >> 5;
    int lane = tid & 31;
    int g    = lane >> 2;
    int q    = lane & 3;
    int hh   = blockIdx.y;          // head 0..7
    int i0   = blockIdx.x * 128;

    const uint32_t* kpg[2] = { g_kp + (size_t)hh*NSEQ*16,
                               g_kp + (size_t)(8+hh)*NSEQ*16 };
    const uint32_t* vpg[2] = { g_vp + (size_t)hh*32*1024,
                               g_vp + (size_t)(8+hh)*32*1024 };
    const float*    bp     = bias + (size_t)hh*NSEQ*NSEQ + (size_t)i0*NSEQ;

    // ---- Q a-frags for both batches ----
    uint32_t qa[2][2][4];
    #pragma unroll
    for (int b = 0; b < 2; ++b) {
        const uint32_t* qpg = g_qp + ((size_t)(b*8+hh)*NSEQ + i0)*16;
        int r0 = w*16 + g;
        #pragma unroll
        for (int ks = 0; ks < 2; ++ks) {
            qa[b][ks][0] = qpg[(size_t)(r0    )*16 + ks*8 + q    ];
            qa[b][ks][1] = qpg[(size_t)(r0 + 8)*16 + ks*8 + q    ];
            qa[b][ks][2] = qpg[(size_t)(r0    )*16 + ks*8 + q + 4];
            qa[b][ks][3] = qpg[(size_t)(r0 + 8)*16 + ks*8 + q + 4];
        }
    }

    uint32_t sb = smem_u32(smem);

    #define PREFETCH_TILE(stg, JT)                                               \
    do {                                                                         \
        uint32_t kvo = sb + (uint32_t)(stg)*(4864u*4u);                          \
        {   /* K both batches: 64 rows x 16 u32, row stride 20 */                \
            int r = tid >> 2, seg = tid & 3;                                     \
            cp16(kvo + (uint32_t)(r*20 + seg*4)*4u,                              \
                 kpg[0] + (size_t)((JT) + r)*16 + seg*4);                        \
            cp16(kvo + (1280u + (uint32_t)(r*20 + seg*4))*4u,                    \
                 kpg[1] + (size_t)((JT) + r)*16 + seg*4);                        \
        }                                                                        \
        {   /* V both batches: 32 rows x 8 u32-of-4, row stride 36 */            \
            int r = tid >> 3, seg = tid & 7;                                     \
            cp16(kvo + (2560u + (uint32_t)(r*36 + seg*4))*4u,                    \
                 vpg[0] + (size_t)r*1024 + ((JT) >> 1) + seg*4);                 \
            cp16(kvo + (3712u + (uint32_t)(r*36 + seg*4))*4u,                    \
                 vpg[1] + (size_t)r*1024 + ((JT) >> 1) + seg*4);                 \
        }                                                                        \
        {   /* bias: 128 rows x 16 float4, swz c4^=row&15 */                     \
            uint32_t bo = sb + (9728u + (uint32_t)(stg)*8192u)*4u;               \
            _Pragma("unroll")                                                    \
            for (int u = 0; u < 8; ++u) {                                        \
                int f   = u*256 + tid;                                           \
                int row = f >> 4;                                                \
                int c4  = f & 15;                                                \
                cp16(bo + (uint32_t)((row*16 + (c4 ^ (row & 15))) << 4),         \
                     bp + (size_t)row*NSEQ + (JT) + c4*4);                       \
            }                                                                    \
        }                                                                        \
        CP_COMMIT();                                                             \
    } while (0)

    PREFETCH_TILE(0, 0);

    float oc[2][4][4] = {};
    float lsum[2][2] = {};
    const int r0l = w*16 + g;

    for (int it = 0; it < 32; ++it) {
        if (it + 1 < 32) {
            PREFETCH_TILE((it+1) & 1, (it+1)*64);
            CP_WAIT(1);
        } else {
            CP_WAIT(0);
        }
        __syncthreads();

        const uint32_t* KV = smemu + (it & 1)*4864;
        const float*    Bs = smem + 9728 + (it & 1)*8192;

        #pragma unroll
        for (int b = 0; b < 2; ++b) {
            const uint32_t* Ks = KV + b*1280;
            const uint32_t* Vs = KV + 2560 + b*1152;

            // ---- S = Q K^T ----
            float c[8][4] = {};
            #pragma unroll
            for (int js = 0; js < 8; ++js) {
                int rb = (js*8 + g)*20;
                #pragma unroll
                for (int ks = 0; ks < 2; ++ks) {
                    uint32_t bb[2];
                    bb[0] = Ks[rb + ks*8 + q    ];
                    bb[1] = Ks[rb + ks*8 + q + 4];
                    mma_f16(c[js], qa[b][ks], bb);
                }
            }

            // ---- softmax: bias from smem, exp, row sums ----
            #pragma unroll
            for (int s = 0; s < 8; ++s) {
                int c4l = s*2 + (q >> 1);
                int e   = 2*(q & 1);
                float2 bv0 = *(const float2*)&Bs[(r0l  )*64 + ((c4l ^ ( r0l      & 15)) << 2) + e];
                float2 bv1 = *(const float2*)&Bs[(r0l+8)*64 + ((c4l ^ ((r0l + 8) & 15)) << 2) + e];
                c[s][0] = __expf(c[s][0] + bv0.x);
                c[s][1] = __expf(c[s][1] + bv0.y);
                c[s][2] = __expf(c[s][2] + bv1.x);
                c[s][3] = __expf(c[s][3] + bv1.y);
                lsum[b][0] += c[s][0] + c[s][1];
                lsum[b][1] += c[s][2] + c[s][3];
            }

            // ---- O += P V (c-frags are a-frags; pack only) ----
            #pragma unroll
            for (int m = 0; m < 4; ++m) {
                uint32_t pa[4];
                pa[0] = packf16(c[2*m  ][1], c[2*m  ][0]);
                pa[1] = packf16(c[2*m  ][3], c[2*m  ][2]);
                pa[2] = packf16(c[2*m+1][1], c[2*m+1][0]);
                pa[3] = packf16(c[2*m+1][3], c[2*m+1][2]);
                #pragma unroll
                for (int ns = 0; ns < 4; ++ns) {
                    int rb = (ns*8 + g)*36;
                    uint32_t bb[2];
                    bb[0] = Vs[rb + m*8 + q    ];
                    bb[1] = Vs[rb + m*8 + q + 4];
                    mma_f16(oc[b][ns], pa, bb);
                }
            }
        }
        __syncthreads();
    }

    // ---- finalize both batches ----
    #pragma unroll
    for (int b = 0; b < 2; ++b) {
        float l0 = lsum[b][0], l1 = lsum[b][1];
        #pragma unroll
        for (int ofs = 1; ofs <= 2; ofs <<= 1) {
            l0 += __shfl_xor_sync(0xffffffffu, l0, ofs);
            l1 += __shfl_xor_sync(0xffffffffu, l1, ofs);
        }
        float inv0 = 1.0f / l0;
        float inv1 = 1.0f / l1;

        int r0 = i0 + w*16 + g;
        size_t base0 = (size_t)(b*NSEQ + r0    )*128 + hh*16;
        size_t base1 = (size_t)(b*NSEQ + r0 + 8)*128 + hh*16;
        #pragma unroll
        for (int ns = 0; ns < 4; ++ns) {
            float ax = oc[b][ns][0]*inv0, ay = oc[b][ns][1]*inv0;
            float bx = oc[b][ns][2]*inv1, by = oc[b][ns][3]*inv1;
            uint32_t ph0 = packf16(ay, ax);
            uint32_t pl0 = packf16(ay - f16hi(ph0), ax - f16lo(ph0));
            uint32_t ph1 = packf16(by, bx);
            uint32_t pl1 = packf16(by - f16hi(ph1), bx - f16lo(ph1));
            int colp = ns*4 + q;
            g_oh[base0 + colp] = ph0;  g_ol[base0 + colp] = pl0;
            g_oh[base1 + colp] = ph1;  g_ol[base1 + colp] = pl1;
        }
    }
}

// ---------------- launch ----------------------------------------------------
extern "C" void kernel_launch(void* const* d_in, const int* in_sizes, int n_in,
                              void* d_out, int out_size)
{
    const float* x        = (const float*)d_in[0];
    const float* rel_bias = (const float*)d_in[1];
    const float* ln_scale = (const float*)d_in[2];
    const float* w_qkv    = (const float*)d_in[3];
    const float* w_out    = (const float*)d_in[4];
    const float* b_out    = (const float*)d_in[5];
    float*       out      = (float*)d_out;

    ln_kernel<<<ROWS, 128>>>(x, ln_scale);

    {   // pack weights to fp16
        uint32_t *w1h, *w2h;
        cudaGetSymbolAddress((void**)&w1h, g_w1h);
        cudaGetSymbolAddress((void**)&w2h, g_w2h);
        int tot1 = (DIM/2)*(3*INNER);
        int tot2 = (INNER/2)*DIM;
        pack_w_kernel<<<(tot1+255)/256, 256>>>(w_qkv, w1h, 3*INNER, tot1);
        pack_w_kernel<<<(tot2+255)/256, 256>>>(w_out, w2h, DIM, tot2);
    }

    dim3 g1(3*INNER/64, ROWS/128);    // (12, 32)
    gemm_qkv_tc<<<g1, 256>>>();

    dim3 gv(NSEQ/128, BATCH*HEADS);   // (16, 16)
    vpack_kernel<<<gv, 256>>>();

    static int att_attr_set = 0;
    if (!att_attr_set) {
        cudaFuncSetAttribute(attn_mma_kernel,
                             cudaFuncAttributeMaxDynamicSharedMemorySize,
                             ATT_SMEM_BYTES);
        att_attr_set = 1;
    }
    dim3 g2(NSEQ/128, HEADS);         // (16, 8) — batch-fused
    attn_mma_kernel<<<g2, 256, ATT_SMEM_BYTES>>>(rel_bias);

    dim3 g3(DIM/64, ROWS/128);        // (8, 32)
    gemm_out_tc<<<g3, 256>>>(b_out, out);
}